// round 8
// baseline (speedup 1.0000x reference)
#include <cuda_runtime.h>
#include <cuda_bf16.h>

// ManifoldConstrainedHyperConnection — fused, G=4, warp-specialized router,
// group-level software pipelining: the next group's x is loaded in 4 waves
// interleaved with the current group's router-partial FMA sets, so its
// stream-mean is already in registers when the next iteration starts.
//
// 576 threads/CTA = 16 worker warps + 2 router warps. 2-slot smem ring
// (sP/sRaw/sM). Workers: [B(g) ⊗ A-loads(g+1) -> arrive FULL(s)] then
// [sync DONE(s^1) (pre-satisfied) -> mix+store g-1]. Routers: reduce 96
// partials + softmax + sinkhorn, publish M a full group ahead of use.
// Wr (192KB) in smem; 4-float d-slice per worker thread; x read twice
// (pipelined mean-read + L2-hit mix-read); prefetch.global.L2 two groups out.

#define WRK 24
#define DDIM 2048
#define WS 4
#define THREADS 576
#define WWARPS 16
#define G 4
#define EPSV 1e-6f

#define SP_STRIDE 100
#define SP_SLOT (WWARPS * SP_STRIDE)
#define SMEM_WR (WRK * DDIM)
#define OFF_SP   SMEM_WR
#define OFF_RAW  (OFF_SP + 2 * SP_SLOT)
#define OFF_M    (OFF_RAW + 2 * 96)
#define SMEM_FLOATS (OFF_M + 2 * 64)
#define SMEM_BYTES (SMEM_FLOATS * 4)

#define FULLM 0xffffffffu

// named barriers: FULL_s = 1+s (workers arrive, routers sync),
//                 DONE_s = 3+s (routers arrive, workers sync), router-internal 5
#define BAR_ARRIVE(id)    asm volatile("bar.arrive %0, %1;" :: "r"(id), "r"(THREADS) : "memory")
#define BAR_SYNC_ALL(id)  asm volatile("bar.sync %0, %1;"   :: "r"(id), "r"(THREADS) : "memory")
#define BAR_SYNC_R(id)    asm volatile("bar.sync %0, %1;"   :: "r"(id), "r"(64) : "memory")

__device__ __forceinline__ float4 ld_cg4(const float* p) {
    return __ldcg(reinterpret_cast<const float4*>(p));
}

#define BFLY_STEP(r, n, o)                                              \
    {                                                                   \
        const bool hi_ = (lane & (o)) != 0;                             \
        _Pragma("unroll")                                               \
        for (int v_ = 0; v_ < (n) / 2; v_++) {                          \
            float mine_  = hi_ ? r[v_ + (n) / 2] : r[v_];               \
            float other_ = hi_ ? r[v_] : r[v_ + (n) / 2];               \
            r[v_] = mine_ + __shfl_xor_sync(FULLM, other_, (o));        \
        }                                                               \
    }

__global__ void __launch_bounds__(THREADS, 1)
mchc_kernel(const float* __restrict__ x, const float* __restrict__ Wr,
            const float* __restrict__ br, float* __restrict__ out, int ntok)
{
    extern __shared__ float sm[];
    float* sWr = sm;

    const int tid  = threadIdx.x;
    const int lane = tid & 31;
    const int warp = tid >> 5;

    for (int i = tid * 4; i < SMEM_WR; i += THREADS * 4)
        *reinterpret_cast<float4*>(sWr + i) = *reinterpret_cast<const float4*>(Wr + i);
    __syncthreads();

    const int ngroups = (ntok + G - 1) / G;
    const int gstride = gridDim.x;

    if (warp < WWARPS) {
        // ================= WORKER PATH (512 threads) =================
        const int d0 = tid * 4;
        int it = 0;
        int gprev = -1;

        // prologue: stream-sum of first group's x into mxc
        float4 mxc[G];
        #pragma unroll
        for (int t = 0; t < G; t++) mxc[t] = make_float4(0.f, 0.f, 0.f, 0.f);
        {
            const int g0 = blockIdx.x;
            if (g0 < ngroups) {
                const int n0 = g0 * G;
                #pragma unroll
                for (int t = 0; t < G; t++) {
                    if (n0 + t < ntok) {
                        const float* p = x + (size_t)(n0 + t) * (WS * DDIM) + d0;
                        #pragma unroll
                        for (int w = 0; w < WS; w++) {
                            float4 v = ld_cg4(p + w * DDIM);
                            mxc[t].x += v.x; mxc[t].y += v.y;
                            mxc[t].z += v.z; mxc[t].w += v.w;
                        }
                    }
                }
            }
        }

        for (int g = blockIdx.x; g < ngroups; g += gstride, it++) {
            const int s  = it & 1;
            float* sP = sm + OFF_SP + s * SP_SLOT;

            // mean of current group (sum already in registers)
            float4 mx[G];
            #pragma unroll
            for (int t = 0; t < G; t++) {
                mx[t].x = mxc[t].x * 0.25f; mx[t].y = mxc[t].y * 0.25f;
                mx[t].z = mxc[t].z * 0.25f; mx[t].w = mxc[t].w * 0.25f;
            }

            // next group's x base (loads interleaved with B below)
            const int gn = g + gstride;
            const bool has_next = (gn < ngroups);
            const int  m0 = gn * G;
            const float* xb = x + (size_t)m0 * (WS * DDIM) + d0;

            float4 nx[G];
            #pragma unroll
            for (int t = 0; t < G; t++) nx[t] = make_float4(0.f, 0.f, 0.f, 0.f);

            // ---- B(g): 3 FMA/butterfly sets, each overlapped with one
            //      4-load wave (stream = set) of group g+1 ----
            float res0, res1, res2;
            #pragma unroll
            for (int set = 0; set < 3; set++) {
                // issue wave loads (stream index = set)
                float4 wv0, wv1, wv2, wv3;
                if (has_next) {
                    wv0 = (m0 + 0 < ntok) ? ld_cg4(xb + 0 * (WS * DDIM) + set * DDIM) : make_float4(0,0,0,0);
                    wv1 = (m0 + 1 < ntok) ? ld_cg4(xb + 1 * (WS * DDIM) + set * DDIM) : make_float4(0,0,0,0);
                    wv2 = (m0 + 2 < ntok) ? ld_cg4(xb + 2 * (WS * DDIM) + set * DDIM) : make_float4(0,0,0,0);
                    wv3 = (m0 + 3 < ntok) ? ld_cg4(xb + 3 * (WS * DDIM) + set * DDIM) : make_float4(0,0,0,0);
                }

                // router partial dots for rows 8*set .. 8*set+7
                float a[32];
                #pragma unroll
                for (int kk = 0; kk < 8; kk++) {
                    const int k = 8 * set + kk;
                    float4 wr = *reinterpret_cast<const float4*>(sWr + k * DDIM + d0);
                    #pragma unroll
                    for (int t = 0; t < G; t++)
                        a[kk * 4 + t] = wr.x * mx[t].x + wr.y * mx[t].y +
                                        wr.z * mx[t].z + wr.w * mx[t].w;
                }
                BFLY_STEP(a, 32, 16)
                BFLY_STEP(a, 16, 8)
                BFLY_STEP(a, 8, 4)
                BFLY_STEP(a, 4, 2)
                BFLY_STEP(a, 2, 1)
                if (set == 0) res0 = a[0];
                else if (set == 1) res1 = a[0];
                else res2 = a[0];

                // fold wave arrivals into next-group stream sums
                if (has_next) {
                    nx[0].x += wv0.x; nx[0].y += wv0.y; nx[0].z += wv0.z; nx[0].w += wv0.w;
                    nx[1].x += wv1.x; nx[1].y += wv1.y; nx[1].z += wv1.z; nx[1].w += wv1.w;
                    nx[2].x += wv2.x; nx[2].y += wv2.y; nx[2].z += wv2.z; nx[2].w += wv2.w;
                    nx[3].x += wv3.x; nx[3].y += wv3.y; nx[3].z += wv3.z; nx[3].w += wv3.w;
                }
            }
            // wave 3 (stream 3) of group g+1
            if (has_next) {
                #pragma unroll
                for (int t = 0; t < G; t++) {
                    if (m0 + t < ntok) {
                        float4 v = ld_cg4(xb + t * (WS * DDIM) + 3 * DDIM);
                        nx[t].x += v.x; nx[t].y += v.y; nx[t].z += v.z; nx[t].w += v.w;
                    }
                }
            }

            sP[warp * SP_STRIDE + lane]      = res0;
            sP[warp * SP_STRIDE + 32 + lane] = res1;
            sP[warp * SP_STRIDE + 64 + lane] = res2;
            BAR_ARRIVE(1 + s);                          // publish sP[s]

            // ---- warm the group after next into L2 (its LDG is next iter) ----
            {
                const int gp = g + 2 * gstride;
                if (gp < ngroups) {
                    const char* pb = reinterpret_cast<const char*>(
                                         x + (size_t)gp * G * (WS * DDIM)) + tid * 256;
                    asm volatile("prefetch.global.L2 [%0];" :: "l"(pb));
                    asm volatile("prefetch.global.L2 [%0];" :: "l"(pb + 128));
                }
            }

            // ---- F(g-1): mix + store previous group ----
            if (gprev >= 0) {
                const int sp = 1 - s;
                BAR_SYNC_ALL(3 + sp);                   // normally pre-satisfied
                const float* sMp = sm + OFF_M + sp * 64;
                const int f0 = gprev * G;
                #pragma unroll
                for (int t = 0; t < G; t++) {
                    if (f0 + t < ntok) {
                        const float* p = x + (size_t)(f0 + t) * (WS * DDIM) + d0;
                        float*       o = out + (size_t)(f0 + t) * (WS * DDIM) + d0;
                        float4 x0 = ld_cg4(p);
                        float4 x1 = ld_cg4(p + DDIM);
                        float4 x2 = ld_cg4(p + 2 * DDIM);
                        float4 x3 = ld_cg4(p + 3 * DDIM);
                        #pragma unroll
                        for (int i = 0; i < WS; i++) {
                            float4 Mi = *reinterpret_cast<const float4*>(sMp + t * 16 + i * 4);
                            float4 ov;
                            ov.x = Mi.x*x0.x + Mi.y*x1.x + Mi.z*x2.x + Mi.w*x3.x;
                            ov.y = Mi.x*x0.y + Mi.y*x1.y + Mi.z*x2.y + Mi.w*x3.y;
                            ov.z = Mi.x*x0.z + Mi.y*x1.z + Mi.z*x2.z + Mi.w*x3.z;
                            ov.w = Mi.x*x0.w + Mi.y*x1.w + Mi.z*x2.w + Mi.w*x3.w;
                            __stcs(reinterpret_cast<float4*>(o + i * DDIM), ov);
                        }
                    }
                }
            }
            gprev = g;
            #pragma unroll
            for (int t = 0; t < G; t++) mxc[t] = nx[t];
        }

        // ---- tail: finish the last group ----
        if (gprev >= 0) {
            const int sp = (it - 1) & 1;
            BAR_SYNC_ALL(3 + sp);
            const float* sMp = sm + OFF_M + sp * 64;
            const int f0 = gprev * G;
            #pragma unroll
            for (int t = 0; t < G; t++) {
                if (f0 + t < ntok) {
                    const float* p = x + (size_t)(f0 + t) * (WS * DDIM) + d0;
                    float*       o = out + (size_t)(f0 + t) * (WS * DDIM) + d0;
                    float4 x0 = ld_cg4(p);
                    float4 x1 = ld_cg4(p + DDIM);
                    float4 x2 = ld_cg4(p + 2 * DDIM);
                    float4 x3 = ld_cg4(p + 3 * DDIM);
                    #pragma unroll
                    for (int i = 0; i < WS; i++) {
                        float4 Mi = *reinterpret_cast<const float4*>(sMp + t * 16 + i * 4);
                        float4 ov;
                        ov.x = Mi.x*x0.x + Mi.y*x1.x + Mi.z*x2.x + Mi.w*x3.x;
                        ov.y = Mi.x*x0.y + Mi.y*x1.y + Mi.z*x2.y + Mi.w*x3.y;
                        ov.z = Mi.x*x0.z + Mi.y*x1.z + Mi.z*x2.z + Mi.w*x3.z;
                        ov.w = Mi.x*x0.w + Mi.y*x1.w + Mi.z*x2.w + Mi.w*x3.w;
                        __stcs(reinterpret_cast<float4*>(o + i * DDIM), ov);
                    }
                }
            }
        }
    } else {
        // ================= ROUTER PATH (warps 16-17) =================
        const int rwarp = warp - WWARPS;
        const int rv    = rwarp * 32 + lane;
        int it = 0;

        for (int g = blockIdx.x; g < ngroups; g += gstride, it++) {
            const int s = it & 1;
            float* sP   = sm + OFF_SP + s * SP_SLOT;
            float* sRaw = sm + OFF_RAW + s * 96;
            float* sM   = sm + OFF_M + s * 64;

            asm volatile("bar.sync %0, %1;" :: "r"(1 + s), "r"(THREADS) : "memory");

            {
                float acc = __ldg(br + (rv >> 2));
                #pragma unroll
                for (int w = 0; w < WWARPS; w++)
                    acc += sP[w * SP_STRIDE + rv];
                sRaw[rv] = acc;
                if (rv < 32) {
                    const int v2 = 64 + rv;
                    float acc2 = __ldg(br + (v2 >> 2));
                    #pragma unroll
                    for (int w = 0; w < WWARPS; w++)
                        acc2 += sP[w * SP_STRIDE + v2];
                    sRaw[v2] = acc2;
                }
            }
            BAR_SYNC_R(5);

            {
                const int t = 2 * rwarp + (lane >> 4);

                float p0 = sRaw[0*4+t], p1 = sRaw[1*4+t], p2 = sRaw[2*4+t], p3 = sRaw[3*4+t];
                float mp = fmaxf(fmaxf(p0, p1), fmaxf(p2, p3));
                p0 = __expf(p0 - mp); p1 = __expf(p1 - mp);
                p2 = __expf(p2 - mp); p3 = __expf(p3 - mp);
                float isp = __fdividef(1.f, p0 + p1 + p2 + p3);
                p0 *= isp; p1 *= isp; p2 *= isp; p3 *= isp;

                float q0 = sRaw[4*4+t], q1 = sRaw[5*4+t], q2 = sRaw[6*4+t], q3 = sRaw[7*4+t];
                float mq = fmaxf(fmaxf(q0, q1), fmaxf(q2, q3));
                q0 = __expf(q0 - mq); q1 = __expf(q1 - mq);
                q2 = __expf(q2 - mq); q3 = __expf(q3 - mq);
                float isq = __fdividef(1.f, q0 + q1 + q2 + q3);
                q0 *= isq; q1 *= isq; q2 *= isq; q3 *= isq;

                float av[16];
                #pragma unroll
                for (int i = 0; i < 4; i++)
                    #pragma unroll
                    for (int j = 0; j < 4; j++)
                        av[i*4+j] = __expf(sRaw[(8 + i*4 + j)*4 + t] + (i == j ? 2.0f : -2.0f));

                #pragma unroll
                for (int itn = 0; itn < 4; itn++) {
                    #pragma unroll
                    for (int i = 0; i < 4; i++) {
                        float rs  = av[i*4] + av[i*4+1] + av[i*4+2] + av[i*4+3];
                        float inv = __fdividef(1.f, fmaxf(rs, EPSV));
                        av[i*4] *= inv; av[i*4+1] *= inv; av[i*4+2] *= inv; av[i*4+3] *= inv;
                    }
                    #pragma unroll
                    for (int j = 0; j < 4; j++) {
                        float cs  = av[j] + av[4+j] + av[8+j] + av[12+j];
                        float inv = __fdividef(1.f, fmaxf(cs, EPSV));
                        av[j] *= inv; av[4+j] *= inv; av[8+j] *= inv; av[12+j] *= inv;
                    }
                }

                if ((lane & 15) == 0) {
                    const float pre[4]  = {p0, p1, p2, p3};
                    const float post[4] = {q0, q1, q2, q3};
                    #pragma unroll
                    for (int i = 0; i < 4; i++) {
                        float4 mrow;
                        mrow.x = av[i*4+0] + post[i] * pre[0];
                        mrow.y = av[i*4+1] + post[i] * pre[1];
                        mrow.z = av[i*4+2] + post[i] * pre[2];
                        mrow.w = av[i*4+3] + post[i] * pre[3];
                        *reinterpret_cast<float4*>(sM + t * 16 + i * 4) = mrow;
                    }
                }
            }
            BAR_ARRIVE(3 + s);
        }
    }
}

extern "C" void kernel_launch(void* const* d_in, const int* in_sizes, int n_in,
                              void* d_out, int out_size)
{
    const float* x  = (const float*)d_in[0];
    const float* Wr = (const float*)d_in[1];
    const float* br = (const float*)d_in[2];
    float* out = (float*)d_out;

    int ntok = in_sizes[0] / (WS * DDIM);   // 8192

    cudaFuncSetAttribute(mchc_kernel,
                         cudaFuncAttributeMaxDynamicSharedMemorySize, SMEM_BYTES);

    int sms = 148, dev = 0;
    if (cudaGetDevice(&dev) == cudaSuccess) {
        int v = 0;
        if (cudaDeviceGetAttribute(&v, cudaDevAttrMultiProcessorCount, dev) == cudaSuccess && v > 0)
            sms = v;
    }
    int ngroups = (ntok + G - 1) / G;
    int grid = (ngroups < sms) ? ngroups : sms;

    mchc_kernel<<<grid, THREADS, SMEM_BYTES>>>(x, Wr, br, out, ntok);
}